// round 10
// baseline (speedup 1.0000x reference)
#include <cuda_runtime.h>
#include <cuda_bf16.h>
#include <cstdint>

// ROI Align (torchvision semantics), OUT 7x7, adaptive grid <= 4x4.
// features: [B=4, C=256, H=200, W=272] fp32 NCHW
// rois:     [N=512, 5] (b, x1, y1, x2, y2) fp32
// out:      [N, C, 7, 7] fp32
//
// R10: occupancy + balance pass on the R9 winner:
//  - 512-thread blocks: 4 CTAs/SM (warp-limited) = 2048 thr/SM = 100% occ
//  - phase 2: exactly one (bin, channel) per thread (392 active) -- no bin
//    loop, no 2:1 warp imbalance
//  - full (gh,gw) template specialization: straight-line tap code, batched LDS

#define OUT_H 7
#define OUT_W 7
#define NBINS 49
#define MAXG  4
#define C_TILE 8
#define REG   30               // max staged rows
#define WCOLS 36               // staged row pitch in floats (144B)
#define CPITCH 1084            // floats per channel: 30*36 +4 pad; %32==28,
                               // *4 %16==0 (bulk dst align)

#define FEAT_C 256
#define FEAT_H 200
#define FEAT_W 272
#define FEAT_HW (FEAT_H * FEAT_W)

__device__ __forceinline__ uint32_t smem_u32(const void* p) {
    uint32_t a;
    asm("{ .reg .u64 t; cvta.to.shared.u64 t, %1; cvt.u32.u64 %0, t; }"
        : "=r"(a) : "l"(p));
    return a;
}

struct __align__(16) SmemLayout {
    float    region[C_TILE * CPITCH];   // [c][row][36]
    float    s_out[C_TILE * NBINS];
    float4   ymeta[OUT_H * MAXG];       // wy0, wy1, rl*36, rh*36
    float4   xmeta[OUT_H * MAXG];       // wx0, wx1, cl, ch
    unsigned long long mbar;
};

// one bin, one channel, fully unrolled taps. 8 lanes share tap addresses.
template<int GH, int GW>
__device__ __forceinline__ float bin_acc(const float* __restrict__ regc,
                                         const float4* __restrict__ ym,
                                         const float4* __restrict__ xm)
{
    float wx0[GW], wx1[GW];
    int   cl[GW],  ch[GW];
    #pragma unroll
    for (int ix = 0; ix < GW; ++ix) {
        const float4 mx = xm[ix];
        wx0[ix] = mx.x;  wx1[ix] = mx.y;
        cl[ix] = __float_as_int(mx.z);
        ch[ix] = __float_as_int(mx.w);
    }
    float acc = 0.0f;
    #pragma unroll
    for (int iy = 0; iy < GH; ++iy) {
        const float4 my = ym[iy];
        const float* rlo = regc + __float_as_int(my.z);
        const float* rhi = regc + __float_as_int(my.w);
        float ra0 = 0.0f, ra1 = 0.0f;
        #pragma unroll
        for (int ix = 0; ix < GW; ++ix) {
            ra0 += wx0[ix] * rlo[cl[ix]] + wx1[ix] * rlo[ch[ix]];
            ra1 += wx0[ix] * rhi[cl[ix]] + wx1[ix] * rhi[ch[ix]];
        }
        acc += my.x * ra0 + my.y * ra1;
    }
    return acc;
}

template<int GH, int GW>
__device__ __forceinline__ void compute_bins(const SmemLayout& sm, float* s_out, int tid)
{
    const int c   = tid & (C_TILE - 1);
    const int bin = tid >> 3;             // one bin per thread
    if (bin < NBINS) {
        const int ph = bin / OUT_W;
        const int pw = bin - ph * OUT_W;
        const float4* ym = sm.ymeta + ph * MAXG;
        const float4* xm = sm.xmeta + pw * MAXG;
        const float* regc = sm.region + c * CPITCH;
        constexpr float inv = 1.0f / (float)(GH * GW);
        s_out[c * NBINS + bin] = bin_acc<GH, GW>(regc, ym, xm) * inv;
    }
}

__global__ __launch_bounds__(512)
void roi_align_kernel(const float* __restrict__ feat,
                      const float* __restrict__ rois,
                      float* __restrict__ out)
{
    __shared__ SmemLayout sm;

    const int H = FEAT_H, W = FEAT_W;
    const int blk = blockIdx.x;
    const int n   = blk & 511;        // roi index
    const int ct  = blk >> 9;         // channel tile (slice-major for L2 reuse)

    const float* r = rois + n * 5;
    const int   bidx  = (int)r[0];
    const float x1    = r[1];
    const float y1    = r[2];
    const float roi_w = fmaxf(r[3] - x1, 1.0f);
    const float roi_h = fmaxf(r[4] - y1, 1.0f);
    const float bin_h = roi_h * (1.0f / OUT_H);
    const float bin_w = roi_w * (1.0f / OUT_W);
    int gh = (int)ceilf(roi_h * (1.0f / OUT_H)); gh = min(max(gh, 1), MAXG);
    int gw = (int)ceilf(roi_w * (1.0f / OUT_W)); gw = min(max(gw, 1), MAXG);

    const int ry0 = min(max((int)floorf(y1), 0), H - 1);
    const int rx0 = min(max((int)floorf(x1), 0), W - 1);
    const int ax0 = min(rx0 & ~3, W - WCOLS);   // aligned window, in-bounds

    // dynamic staged extent
    const int ymax = min((int)floorf(y1 + roi_h) + 1, H - 1);
    const int rows_used = min(REG, ymax - ry0 + 1);             // >= 1
    const int xmax = min((int)floorf(x1 + roi_w) + 1, W - 1);
    const int cols_f = min(WCOLS, ((xmax - ax0 + 1 + 3) & ~3)); // mult of 4
    const int cols_bytes = cols_f * 4;                          // mult of 16

    const int tid = threadIdx.x;
    const uint32_t mbar = smem_u32(&sm.mbar);

    // ---- init mbarrier + expect exact staging byte count ----
    if (tid == 0) {
        asm volatile("mbarrier.init.shared.b64 [%0], 1;" :: "r"(mbar) : "memory");
        asm volatile("mbarrier.arrive.expect_tx.shared.b64 _, [%0], %1;"
                     :: "r"(mbar), "r"(C_TILE * rows_used * cols_bytes) : "memory");
    }
    __syncthreads();

    // ---- phase 1: enqueue bulk row copies (shift/mask mapping) ----
    if (tid < 256) {
        const int c   = tid >> 5;         // 0..7
        const int row = tid & 31;         // 0..31; rows >= rows_used skipped
        if (row < rows_used) {
            const float* src = feat
                + ((size_t)bidx * FEAT_C + (size_t)(ct * C_TILE + c)) * (size_t)FEAT_HW
                + (size_t)(ry0 + row) * W + ax0;
            const uint32_t dst = smem_u32(sm.region)
                               + (uint32_t)((c * CPITCH + row * WCOLS) * 4);
            asm volatile(
                "cp.async.bulk.shared::cluster.global.mbarrier::complete_tx::bytes "
                "[%0], [%1], %2, [%3];"
                :: "r"(dst), "l"(src), "r"(cols_bytes), "r"(mbar) : "memory");
        }
    }

    // ---- phase 0 (overlapped with DMA): weights + premult clamped offsets ----
    if (tid >= 256 && tid < 256 + 2 * OUT_H * MAXG) {
        const int  w   = tid - 256;
        const bool isx = (w >= OUT_H * MAXG);
        const int  t   = isx ? w - OUT_H * MAXG : w;
        const int  p   = t >> 2;          // output bin index along axis
        const int  gg  = t & 3;           // grid slot
        const float start = isx ? x1 : y1;
        const float binsz = isx ? bin_w : bin_h;
        const int   gcnt  = isx ? gw : gh;
        const int   size  = isx ? W : H;
        const float pos = start + (float)p * binsz + ((float)gg + 0.5f) * binsz / (float)gcnt;
        const bool valid = (pos >= -1.0f) && (pos <= (float)size);
        float pp = fmaxf(pos, 0.0f);
        int low = min((int)floorf(pp), size - 1);
        if (low >= size - 1) pp = (float)(size - 1);
        const float frac = pp - (float)low;
        const float m = valid ? 1.0f : 0.0f;
        const int hi = min(low + 1, size - 1);
        float4 mv;
        mv.x = (1.0f - frac) * m;
        mv.y = frac * m;
        if (isx) {
            mv.z = __int_as_float(min(max(low - ax0, 0), cols_f - 1));
            mv.w = __int_as_float(min(max(hi  - ax0, 0), cols_f - 1));
            sm.xmeta[t] = mv;
        } else {
            mv.z = __int_as_float(min(max(low - ry0, 0), rows_used - 1) * WCOLS);
            mv.w = __int_as_float(min(max(hi  - ry0, 0), rows_used - 1) * WCOLS);
            sm.ymeta[t] = mv;
        }
    }

    // ---- wait for DMA completion (parity 0: fresh barrier each launch) ----
    asm volatile(
        "{\n\t"
        ".reg .pred P;\n\t"
        "WAIT_%=:\n\t"
        "mbarrier.try_wait.parity.acquire.cta.shared::cta.b64 P, [%0], 0, 0x989680;\n\t"
        "@P bra DONE_%=;\n\t"
        "bra WAIT_%=;\n\t"
        "DONE_%=:\n\t"
        "}"
        :: "r"(mbar) : "memory");
    __syncthreads();   // also covers meta visibility

    // ---- phase 2: one (bin, channel) per thread; (gh,gw)-specialized ----
    {
        switch ((gh - 1) * 4 + (gw - 1)) {
            case 0:  compute_bins<1,1>(sm, sm.s_out, tid); break;
            case 1:  compute_bins<1,2>(sm, sm.s_out, tid); break;
            case 2:  compute_bins<1,3>(sm, sm.s_out, tid); break;
            case 3:  compute_bins<1,4>(sm, sm.s_out, tid); break;
            case 4:  compute_bins<2,1>(sm, sm.s_out, tid); break;
            case 5:  compute_bins<2,2>(sm, sm.s_out, tid); break;
            case 6:  compute_bins<2,3>(sm, sm.s_out, tid); break;
            case 7:  compute_bins<2,4>(sm, sm.s_out, tid); break;
            case 8:  compute_bins<3,1>(sm, sm.s_out, tid); break;
            case 9:  compute_bins<3,2>(sm, sm.s_out, tid); break;
            case 10: compute_bins<3,3>(sm, sm.s_out, tid); break;
            case 11: compute_bins<3,4>(sm, sm.s_out, tid); break;
            case 12: compute_bins<4,1>(sm, sm.s_out, tid); break;
            case 13: compute_bins<4,2>(sm, sm.s_out, tid); break;
            case 14: compute_bins<4,3>(sm, sm.s_out, tid); break;
            default: compute_bins<4,4>(sm, sm.s_out, tid); break;
        }
    }
    __syncthreads();

    // ---- phase 3: coalesced float4 output write ----
    {
        float4* ob4 = (float4*)(out + ((size_t)n * FEAT_C + (size_t)ct * C_TILE) * NBINS);
        const float4* so4 = (const float4*)sm.s_out;
        if (tid < (C_TILE * NBINS) / 4)      // 98 threads x 16B
            ob4[tid] = so4[tid];
    }
}

extern "C" void kernel_launch(void* const* d_in, const int* in_sizes, int n_in,
                              void* d_out, int out_size)
{
    const float* feat = (const float*)d_in[0];
    const float* rois = (const float*)d_in[1];
    float* out = (float*)d_out;
    const int N = in_sizes[1] / 5;

    roi_align_kernel<<<N * (FEAT_C / C_TILE), 512>>>(feat, rois, out);
}

// round 11
// speedup vs baseline: 1.0339x; 1.0339x over previous
#include <cuda_runtime.h>
#include <cuda_bf16.h>
#include <cstdint>

// ROI Align (torchvision semantics), OUT 7x7, adaptive grid <= 4x4.
// features: [B=4, C=256, H=200, W=272] fp32 NCHW
// rois:     [N=512, 5] (b, x1, y1, x2, y2) fp32
// out:      [N, C, 7, 7] fp32
//
// R11: R9 winner + balanced phase 2:
//  - 416-thread blocks (13 warps): threads 0..391 take exactly one
//    (bin, channel) item -> phase-2 critical path 2 bins -> 1 bin,
//    R9's 4-distinct-address LDS broadcast pattern preserved
//  - gw-only templates (4 small variants; R10's 16-way switch hurt I-cache)
//  - phase 0 on threads 256.. so it overlaps phase-1 DMA enqueue

#define OUT_H 7
#define OUT_W 7
#define NBINS 49
#define MAXG  4
#define C_TILE 8
#define REG   30               // max staged rows
#define WCOLS 36               // staged row pitch in floats (144B)
#define CPITCH 1084            // floats per channel: 30*36 +4 pad; %32==28,
                               // *4 %16==0 (bulk dst align)
#define NTHREADS 416

#define FEAT_C 256
#define FEAT_H 200
#define FEAT_W 272
#define FEAT_HW (FEAT_H * FEAT_W)

__device__ __forceinline__ uint32_t smem_u32(const void* p) {
    uint32_t a;
    asm("{ .reg .u64 t; cvta.to.shared.u64 t, %1; cvt.u32.u64 %0, t; }"
        : "=r"(a) : "l"(p));
    return a;
}

struct __align__(16) SmemLayout {
    float    region[C_TILE * CPITCH];   // [c][row][36]
    float    s_out[C_TILE * NBINS];
    float4   ymeta[OUT_H * MAXG];       // wy0, wy1, rl*36, rh*36
    float4   xmeta[OUT_H * MAXG];       // wx0, wx1, cl, ch
    unsigned long long mbar;
};

// one bin, one channel. x-meta in registers; lanes share tap addresses.
template<int GW>
__device__ __forceinline__ float bin_acc(const float* __restrict__ regc,
                                         const float4* __restrict__ ym,
                                         const float4* __restrict__ xm,
                                         int gh)
{
    float wx0[GW], wx1[GW];
    int   cl[GW],  ch[GW];
    #pragma unroll
    for (int ix = 0; ix < GW; ++ix) {
        const float4 mx = xm[ix];
        wx0[ix] = mx.x;  wx1[ix] = mx.y;
        cl[ix] = __float_as_int(mx.z);
        ch[ix] = __float_as_int(mx.w);
    }
    float acc = 0.0f;
    for (int iy = 0; iy < gh; ++iy) {
        const float4 my = ym[iy];
        const float* rlo = regc + __float_as_int(my.z);
        const float* rhi = regc + __float_as_int(my.w);
        float ra0 = 0.0f, ra1 = 0.0f;
        #pragma unroll
        for (int ix = 0; ix < GW; ++ix) {
            ra0 += wx0[ix] * rlo[cl[ix]] + wx1[ix] * rlo[ch[ix]];
            ra1 += wx0[ix] * rhi[cl[ix]] + wx1[ix] * rhi[ch[ix]];
        }
        acc += my.x * ra0 + my.y * ra1;
    }
    return acc;
}

// one (bin, channel) item per thread; 392 active of 416
template<int GW>
__device__ __forceinline__ void compute_bins(const SmemLayout& sm, float* s_out,
                                             int tid, int gh, float inv)
{
    if (tid < NBINS * C_TILE) {
        const int c   = tid & (C_TILE - 1);
        const int bin = tid >> 3;
        const int ph  = bin / OUT_W;
        const int pw  = bin - ph * OUT_W;
        const float4* ym = sm.ymeta + ph * MAXG;
        const float4* xm = sm.xmeta + pw * MAXG;
        const float* regc = sm.region + c * CPITCH;
        s_out[c * NBINS + bin] = bin_acc<GW>(regc, ym, xm, gh) * inv;
    }
}

__global__ __launch_bounds__(NTHREADS)
void roi_align_kernel(const float* __restrict__ feat,
                      const float* __restrict__ rois,
                      float* __restrict__ out)
{
    __shared__ SmemLayout sm;

    const int H = FEAT_H, W = FEAT_W;
    const int blk = blockIdx.x;
    const int n   = blk & 511;        // roi index
    const int ct  = blk >> 9;         // channel tile (slice-major for L2 reuse)

    const float* r = rois + n * 5;
    const int   bidx  = (int)r[0];
    const float x1    = r[1];
    const float y1    = r[2];
    const float roi_w = fmaxf(r[3] - x1, 1.0f);
    const float roi_h = fmaxf(r[4] - y1, 1.0f);
    const float bin_h = roi_h * (1.0f / OUT_H);
    const float bin_w = roi_w * (1.0f / OUT_W);
    int gh = (int)ceilf(roi_h * (1.0f / OUT_H)); gh = min(max(gh, 1), MAXG);
    int gw = (int)ceilf(roi_w * (1.0f / OUT_W)); gw = min(max(gw, 1), MAXG);

    const int ry0 = min(max((int)floorf(y1), 0), H - 1);
    const int rx0 = min(max((int)floorf(x1), 0), W - 1);
    const int ax0 = min(rx0 & ~3, W - WCOLS);   // aligned window, in-bounds

    // dynamic staged extent
    const int ymax = min((int)floorf(y1 + roi_h) + 1, H - 1);
    const int rows_used = min(REG, ymax - ry0 + 1);             // >= 1
    const int xmax = min((int)floorf(x1 + roi_w) + 1, W - 1);
    const int cols_f = min(WCOLS, ((xmax - ax0 + 1 + 3) & ~3)); // mult of 4
    const int cols_bytes = cols_f * 4;                          // mult of 16

    const int tid = threadIdx.x;
    const uint32_t mbar = smem_u32(&sm.mbar);

    // ---- init mbarrier + expect exact staging byte count ----
    if (tid == 0) {
        asm volatile("mbarrier.init.shared.b64 [%0], 1;" :: "r"(mbar) : "memory");
        asm volatile("mbarrier.arrive.expect_tx.shared.b64 _, [%0], %1;"
                     :: "r"(mbar), "r"(C_TILE * rows_used * cols_bytes) : "memory");
    }
    __syncthreads();

    // ---- phase 1: enqueue bulk row copies (threads 0..255) ----
    if (tid < 256) {
        const int c   = tid >> 5;         // 0..7
        const int row = tid & 31;         // 0..31; rows >= rows_used skipped
        if (row < rows_used) {
            const float* src = feat
                + ((size_t)bidx * FEAT_C + (size_t)(ct * C_TILE + c)) * (size_t)FEAT_HW
                + (size_t)(ry0 + row) * W + ax0;
            const uint32_t dst = smem_u32(sm.region)
                               + (uint32_t)((c * CPITCH + row * WCOLS) * 4);
            asm volatile(
                "cp.async.bulk.shared::cluster.global.mbarrier::complete_tx::bytes "
                "[%0], [%1], %2, [%3];"
                :: "r"(dst), "l"(src), "r"(cols_bytes), "r"(mbar) : "memory");
        }
    }

    // ---- phase 0 (threads 256.., overlaps DMA enqueue): weights + offsets ----
    if (tid >= 256 && tid < 256 + 2 * OUT_H * MAXG) {
        const int  w   = tid - 256;
        const bool isx = (w >= OUT_H * MAXG);
        const int  t   = isx ? w - OUT_H * MAXG : w;
        const int  p   = t >> 2;          // output bin index along axis
        const int  gg  = t & 3;           // grid slot
        const float start = isx ? x1 : y1;
        const float binsz = isx ? bin_w : bin_h;
        const int   gcnt  = isx ? gw : gh;
        const int   size  = isx ? W : H;
        const float pos = start + (float)p * binsz + ((float)gg + 0.5f) * binsz / (float)gcnt;
        const bool valid = (pos >= -1.0f) && (pos <= (float)size);
        float pp = fmaxf(pos, 0.0f);
        int low = min((int)floorf(pp), size - 1);
        if (low >= size - 1) pp = (float)(size - 1);
        const float frac = pp - (float)low;
        const float m = valid ? 1.0f : 0.0f;
        const int hi = min(low + 1, size - 1);
        float4 mv;
        mv.x = (1.0f - frac) * m;
        mv.y = frac * m;
        if (isx) {
            mv.z = __int_as_float(min(max(low - ax0, 0), cols_f - 1));
            mv.w = __int_as_float(min(max(hi  - ax0, 0), cols_f - 1));
            sm.xmeta[t] = mv;
        } else {
            mv.z = __int_as_float(min(max(low - ry0, 0), rows_used - 1) * WCOLS);
            mv.w = __int_as_float(min(max(hi  - ry0, 0), rows_used - 1) * WCOLS);
            sm.ymeta[t] = mv;
        }
    }

    // ---- wait for DMA completion (parity 0: fresh barrier each launch) ----
    asm volatile(
        "{\n\t"
        ".reg .pred P;\n\t"
        "WAIT_%=:\n\t"
        "mbarrier.try_wait.parity.acquire.cta.shared::cta.b64 P, [%0], 0, 0x989680;\n\t"
        "@P bra DONE_%=;\n\t"
        "bra WAIT_%=;\n\t"
        "DONE_%=:\n\t"
        "}"
        :: "r"(mbar) : "memory");
    __syncthreads();   // also covers meta visibility

    // ---- phase 2: one (bin, channel) item per thread; gw-specialized ----
    {
        const float inv = 1.0f / (float)(gh * gw);
        switch (gw) {
            case 1:  compute_bins<1>(sm, sm.s_out, tid, gh, inv); break;
            case 2:  compute_bins<2>(sm, sm.s_out, tid, gh, inv); break;
            case 3:  compute_bins<3>(sm, sm.s_out, tid, gh, inv); break;
            default: compute_bins<4>(sm, sm.s_out, tid, gh, inv); break;
        }
    }
    __syncthreads();

    // ---- phase 3: coalesced float4 output write ----
    {
        float4* ob4 = (float4*)(out + ((size_t)n * FEAT_C + (size_t)ct * C_TILE) * NBINS);
        const float4* so4 = (const float4*)sm.s_out;
        if (tid < (C_TILE * NBINS) / 4)      // 98 threads x 16B
            ob4[tid] = so4[tid];
    }
}

extern "C" void kernel_launch(void* const* d_in, const int* in_sizes, int n_in,
                              void* d_out, int out_size)
{
    const float* feat = (const float*)d_in[0];
    const float* rois = (const float*)d_in[1];
    float* out = (float*)d_out;
    const int N = in_sizes[1] / 5;

    roi_align_kernel<<<N * (FEAT_C / C_TILE), NTHREADS>>>(feat, rois, out);
}